// round 4
// baseline (speedup 1.0000x reference)
#include <cuda_runtime.h>
#include <cuda_bf16.h>
#include <cstdint>

// ============================================================================
// SwapTestAttention on GB300 — Round 2: packed fma.rn.f32x2 main loop.
//   Phase 1: warp-per-(token,role) 6-qubit circuit sim -> Q/K states, V table.
//   Phase 2: fused fidelity + exp-weighted V accumulation, (re,im) accumulated
//            in ONE packed f32x2 register -> 2 issues per pair per complex dim.
//   Phase 3: deterministic key-split combine + normalize.
// ============================================================================

#define NTOK 8192
#define NQB  6
#define DIM  64
#define NL   2

#define BM 64        // queries per block
#define BN 128       // keys per smem tile
#define KSPLIT 8
#define KEYS_PER_SPLIT (NTOK / KSPLIT)   // 1024
#define NTILES (KEYS_PER_SPLIT / BN)     // 8
#define DR 65        // float4 row stride (64 dims + 1 pad) for Q/K smem tiles

// Scratch (device globals; no allocation allowed)
__device__ float4 g_Q[NTOK * 32];            // [token][32] float4 = 64 float2 (re,im)
__device__ float4 g_K[NTOK * 32];
__device__ float  g_V[NTOK * 8];             // 6 used + pad
__device__ float  g_part[KSPLIT][NTOK][8];   // per-split partial (6 acc + denom)

__device__ __forceinline__ float shfl_x(float v, int m) {
    return __shfl_xor_sync(0xffffffffu, v, m);
}

// ---- packed f32x2 helpers --------------------------------------------------
__device__ __forceinline__ unsigned long long ffma2(
    unsigned long long a, unsigned long long b, unsigned long long c) {
    unsigned long long d;
    asm("fma.rn.f32x2 %0, %1, %2, %3;" : "=l"(d) : "l"(a), "l"(b), "l"(c));
    return d;
}
__device__ __forceinline__ float2 unpk(unsigned long long v) {
    float2 f;
    asm("mov.b64 {%0, %1}, %2;" : "=f"(f.x), "=f"(f.y) : "l"(v));
    return f;
}

// ---------------------------------------------------------------------------
// Phase 1: one warp simulates one (token, role) circuit.
// Lane l holds amplitudes of flat indices n=l (a0, bit5=0) and n=l+32 (a1).
// Qubit q <-> flat bit (5-q): q=0 is the a0/a1 split, q=1..5 are lane bits 4..0.
// ---------------------------------------------------------------------------
__global__ void __launch_bounds__(256) prep_kernel(
    const float* __restrict__ x,
    const float* __restrict__ pq,
    const float* __restrict__ pk,
    const float* __restrict__ pv)
{
    int gw    = (blockIdx.x * 256 + threadIdx.x) >> 5;
    int lane  = threadIdx.x & 31;
    int token = gw & (NTOK - 1);
    int role  = gw >> 13;                  // 0=Q, 1=K, 2=V
    const float* p = (role == 0) ? pq : (role == 1) ? pk : pv;

    float r0 = (lane == 0) ? 1.f : 0.f, i0 = 0.f, r1 = 0.f, i1 = 0.f;

    auto RY = [&](float th, int q) {
        float s, c; __sincosf(0.5f * th, &s, &c);
        if (q == 0) {
            float nr0 = c*r0 - s*r1, ni0 = c*i0 - s*i1;
            float nr1 = s*r0 + c*r1, ni1 = s*i0 + c*i1;
            r0 = nr0; i0 = ni0; r1 = nr1; i1 = ni1;
        } else {
            int m = 1 << (5 - q);
            float pr0 = shfl_x(r0, m), pi0 = shfl_x(i0, m);
            float pr1 = shfl_x(r1, m), pi1 = shfl_x(i1, m);
            float sg = (lane & m) ? s : -s;
            r0 = fmaf(sg, pr0, c*r0); i0 = fmaf(sg, pi0, c*i0);
            r1 = fmaf(sg, pr1, c*r1); i1 = fmaf(sg, pi1, c*i1);
        }
    };
    auto RZ = [&](float th, int q) {
        float s, c; __sincosf(0.5f * th, &s, &c);
        if (q == 0) {
            float nr0 = r0*c + i0*s, ni0 = i0*c - r0*s;
            float nr1 = r1*c - i1*s, ni1 = i1*c + r1*s;
            r0 = nr0; i0 = ni0; r1 = nr1; i1 = ni1;
        } else {
            int m = 1 << (5 - q);
            float sg = (lane & m) ? s : -s;
            float nr0 = r0*c - i0*sg, ni0 = i0*c + r0*sg;
            float nr1 = r1*c - i1*sg, ni1 = i1*c + r1*sg;
            r0 = nr0; i0 = ni0; r1 = nr1; i1 = ni1;
        }
    };

    #pragma unroll
    for (int q = 0; q < NQB; q++) RY(x[token * NQB + q], q);

    #pragma unroll
    for (int l = 0; l < NL; l++) {
        #pragma unroll
        for (int q = 0; q < NQB; q++) {
            RY(p[(l * NQB + q) * 2 + 0], q);
            RZ(p[(l * NQB + q) * 2 + 1], q);
        }
        // CNOT ring
        r1 = shfl_x(r1, 16); i1 = shfl_x(i1, 16);
        #pragma unroll
        for (int q = 1; q <= 4; q++) {
            int cm = 1 << (5 - q), tm = 1 << (4 - q);
            float t;
            t = shfl_x(r0, tm); if (lane & cm) r0 = t;
            t = shfl_x(i0, tm); if (lane & cm) i0 = t;
            t = shfl_x(r1, tm); if (lane & cm) r1 = t;
            t = shfl_x(i1, tm); if (lane & cm) i1 = t;
        }
        if (lane & 1) { float t = r0; r0 = r1; r1 = t; t = i0; i0 = i1; i1 = t; }
    }

    if (role < 2) {
        float2* buf = (role == 0) ? (float2*)g_Q : (float2*)g_K;
        buf[token * DIM + lane]      = make_float2(r0, i0);
        buf[token * DIM + 32 + lane] = make_float2(r1, i1);
    } else {
        float p0 = r0*r0 + i0*i0;
        float p1 = r1*r1 + i1*i1;
        float v[6];
        v[0] = p0 - p1;
        #pragma unroll
        for (int q = 1; q < 6; q++) {
            float sgn = ((lane >> (5 - q)) & 1) ? -1.f : 1.f;
            v[q] = sgn * (p0 + p1);
        }
        #pragma unroll
        for (int off = 16; off >= 1; off >>= 1) {
            #pragma unroll
            for (int q = 0; q < 6; q++) v[q] += __shfl_down_sync(0xffffffffu, v[q], off);
        }
        if (lane == 0) {
            #pragma unroll
            for (int q = 0; q < 6; q++) g_V[token * 8 + q] = v[q];
            g_V[token * 8 + 6] = 0.f;
            g_V[token * 8 + 7] = 0.f;
        }
    }
}

// ---------------------------------------------------------------------------
// Phase 2: fused fidelity + exp-weighted V accumulation, f32x2 main loop.
// Smem per complex dim d:
//   Qs[row][d] = {qr, qi, qi, -qr}   (two packed pairs)
//   Ks[key][d] = {kr, kr, ki, ki}
// acc (packed {re, im}) per pair per dim:
//   acc = ffma2({qr,qi},  {kr,kr}, acc)   -> re += qr*kr ; im += qi*kr
//   acc = ffma2({qi,-qr}, {ki,ki}, acc)   -> re += qi*ki ; im += -qr*ki
// ---------------------------------------------------------------------------
__global__ void __launch_bounds__(256, 1) attn_kernel()
{
    extern __shared__ float4 smem4[];
    float4* Qs = smem4;                           // BM * DR
    float4* Ks = smem4 + BM * DR;                 // BN * DR
    float*  Vs = (float*)(smem4 + (BM + BN) * DR); // BN * 9

    int tid  = threadIdx.x;
    int qt   = blockIdx.x;     // 0..127
    int ks   = blockIdx.y;     // 0..7
    int ncol = tid & 15;
    int mrow = tid >> 4;
    int q0   = qt * BM;

    // load + expand Q tile: g_Q float4 = {r0,i0,r1,i1} (2 complex dims)
    const float4* Qg = g_Q + (size_t)q0 * 32;
    for (int idx = tid; idx < BM * 32; idx += 256) {
        int r = idx >> 5, c = idx & 31;
        float4 v = Qg[idx];
        Qs[r * DR + 2*c + 0] = make_float4(v.x, v.y, v.y, -v.x);
        Qs[r * DR + 2*c + 1] = make_float4(v.z, v.w, v.w, -v.z);
    }

    float den[4] = {0.f, 0.f, 0.f, 0.f};
    float acv[4][6];
    #pragma unroll
    for (int m = 0; m < 4; m++)
        #pragma unroll
        for (int c = 0; c < 6; c++) acv[m][c] = 0.f;

    for (int kt = 0; kt < NTILES; kt++) {
        int key0 = ks * KEYS_PER_SPLIT + kt * BN;
        __syncthreads();   // previous tile fully consumed
        const float4* Kg = g_K + (size_t)key0 * 32;
        for (int idx = tid; idx < BN * 32; idx += 256) {
            int r = idx >> 5, c = idx & 31;
            float4 v = Kg[idx];
            Ks[r * DR + 2*c + 0] = make_float4(v.x, v.x, v.y, v.y);
            Ks[r * DR + 2*c + 1] = make_float4(v.z, v.z, v.w, v.w);
        }
        const float* Vg = g_V + (size_t)key0 * 8;
        for (int idx = tid; idx < BN * 8; idx += 256) {
            int r = idx >> 3, c = idx & 7;
            Vs[r * 9 + c] = Vg[idx];
        }
        __syncthreads();

        unsigned long long acc[4][8];
        #pragma unroll
        for (int m = 0; m < 4; m++)
            #pragma unroll
            for (int n = 0; n < 8; n++) acc[m][n] = 0ull;

        #pragma unroll 2
        for (int d = 0; d < 64; d++) {   // one complex dim per iter
            ulonglong2 qv[4], kv[8];
            #pragma unroll
            for (int m = 0; m < 4; m++)
                qv[m] = *(const ulonglong2*)(Qs + (mrow * 4 + m) * DR + d);
            #pragma unroll
            for (int n = 0; n < 8; n++)
                kv[n] = *(const ulonglong2*)(Ks + (n * 16 + ncol) * DR + d);
            #pragma unroll
            for (int m = 0; m < 4; m++) {
                #pragma unroll
                for (int n = 0; n < 8; n++) {
                    acc[m][n] = ffma2(qv[m].x, kv[n].x, acc[m][n]);
                    acc[m][n] = ffma2(qv[m].y, kv[n].y, acc[m][n]);
                }
            }
        }

        // epilogue: l = re^2+im^2 in [0,1]; accumulate exp(l)*V and exp(l)
        #pragma unroll
        for (int n = 0; n < 8; n++) {
            float vv[6];
            #pragma unroll
            for (int c = 0; c < 6; c++) vv[c] = Vs[(n * 16 + ncol) * 9 + c];
            #pragma unroll
            for (int m = 0; m < 4; m++) {
                float2 ri = unpk(acc[m][n]);
                float l = fmaf(ri.x, ri.x, ri.y * ri.y);
                float w = __expf(l);
                den[m] += w;
                #pragma unroll
                for (int c = 0; c < 6; c++) acv[m][c] = fmaf(w, vv[c], acv[m][c]);
            }
        }
    }

    // reduce partials across the 16 ncol lanes sharing each query
    #pragma unroll
    for (int off = 8; off >= 1; off >>= 1) {
        #pragma unroll
        for (int m = 0; m < 4; m++) {
            den[m] += __shfl_xor_sync(0xffffffffu, den[m], off);
            #pragma unroll
            for (int c = 0; c < 6; c++)
                acv[m][c] += __shfl_xor_sync(0xffffffffu, acv[m][c], off);
        }
    }
    if (ncol == 0) {
        #pragma unroll
        for (int m = 0; m < 4; m++) {
            int qi = q0 + mrow * 4 + m;
            #pragma unroll
            for (int c = 0; c < 6; c++) g_part[ks][qi][c] = acv[m][c];
            g_part[ks][qi][6] = den[m];
        }
    }
}

// ---------------------------------------------------------------------------
// Phase 3: deterministic combine of the 8 key-splits + normalize.
// ---------------------------------------------------------------------------
__global__ void __launch_bounds__(256) finalize_kernel(float* __restrict__ out)
{
    int i = blockIdx.x * 256 + threadIdx.x;
    if (i >= NTOK) return;
    float den = 0.f;
    float num[6] = {0.f, 0.f, 0.f, 0.f, 0.f, 0.f};
    #pragma unroll
    for (int ks = 0; ks < KSPLIT; ks++) {
        den += g_part[ks][i][6];
        #pragma unroll
        for (int c = 0; c < 6; c++) num[c] += g_part[ks][i][c];
    }
    float inv = 1.f / den;
    #pragma unroll
    for (int c = 0; c < 6; c++) out[i * 6 + c] = num[c] * inv;
}

// ---------------------------------------------------------------------------
extern "C" void kernel_launch(void* const* d_in, const int* in_sizes, int n_in,
                              void* d_out, int out_size)
{
    const float* x  = (const float*)d_in[0];  // (8192, 6)
    const float* pq = (const float*)d_in[1];  // (2, 6, 2)
    const float* pk = (const float*)d_in[2];
    const float* pv = (const float*)d_in[3];
    float* out = (float*)d_out;               // (8192, 6) f32

    prep_kernel<<<(NTOK * 3) / 8, 256>>>(x, pq, pk, pv);

    size_t smem = (size_t)(BM + BN) * DR * sizeof(float4) + (size_t)BN * 9 * sizeof(float);
    cudaFuncSetAttribute(attn_kernel, cudaFuncAttributeMaxDynamicSharedMemorySize, (int)smem);
    attn_kernel<<<dim3(NTOK / BM, KSPLIT), 256, smem>>>();

    finalize_kernel<<<NTOK / 256, 256>>>(out);
}

// round 5
// speedup vs baseline: 2.6737x; 2.6737x over previous
#include <cuda_runtime.h>
#include <cuda_bf16.h>
#include <cstdint>

// ============================================================================
// SwapTestAttention on GB300 — Round 4: tf32 tensor-core (mma.sync) main loop.
//   Phase 1: warp-per-(token,role) 6-qubit circuit sim -> Q/K states, V table.
//   Phase 2: fidelity via two tf32 GEMMs over K=128 real dims:
//              re = [Qr|Qi] . [Kr|Ki]^T
//              im = [Qi|-Qr] . [Kr|Ki]^T   (A chunk-swap + negate; B shared)
//            fused epilogue: w=exp(re^2+im^2), accumulate w*V and w.
//   Phase 3: deterministic combine of 32 partial slots + normalize.
// ============================================================================

#define NTOK 8192
#define NQB  6
#define DIM  64
#define NL   2

#define QT   128                 // queries per CTA
#define KT   64                  // keys per smem tile
#define KSPL 16                  // key splits (grid.y)
#define KEYS_PER_CTA (NTOK / KSPL)      // 512
#define NT_TILES (KEYS_PER_CTA / KT)    // 8
#define NSLOT 32                 // 16 splits x 2 n-warps

// smem offsets (floats)
#define AQ_OFF 0                         // [16][128][8] tf32
#define BS_OFF (16*128*8)                // [16][64][8]  tf32
#define VS_OFF (BS_OFF + 16*64*8)        // [64][12]
#define SMEM_FLOATS (VS_OFF + 64*12)     // 25344 floats = 101376 B

// Scratch (device globals; no allocation allowed)
__device__ float4 g_Q[NTOK * 32];            // [token][32] float4 = 64 float2 (re,im)
__device__ float4 g_K[NTOK * 32];
__device__ float  g_V[NTOK * 8];             // 6 used + pad
__device__ float  g_part[NSLOT][NTOK][8];    // partial (6 acc + denom)

__device__ __forceinline__ float shfl_x(float v, int m) {
    return __shfl_xor_sync(0xffffffffu, v, m);
}
__device__ __forceinline__ float to_tf32(float x) {
    float r; asm("cvt.rna.tf32.f32 %0, %1;" : "=f"(r) : "f"(x)); return r;
}
__device__ __forceinline__ void mma_tf32(float d[4],
    uint32_t a0, uint32_t a1, uint32_t a2, uint32_t a3,
    uint32_t b0, uint32_t b1)
{
    asm volatile(
        "mma.sync.aligned.m16n8k8.row.col.f32.tf32.tf32.f32 "
        "{%0,%1,%2,%3}, {%4,%5,%6,%7}, {%8,%9}, {%0,%1,%2,%3};"
        : "+f"(d[0]), "+f"(d[1]), "+f"(d[2]), "+f"(d[3])
        : "r"(a0), "r"(a1), "r"(a2), "r"(a3), "r"(b0), "r"(b1));
}

// ---------------------------------------------------------------------------
// Phase 1: one warp simulates one (token, role) circuit.  (unchanged)
// ---------------------------------------------------------------------------
__global__ void __launch_bounds__(256) prep_kernel(
    const float* __restrict__ x,
    const float* __restrict__ pq,
    const float* __restrict__ pk,
    const float* __restrict__ pv)
{
    int gw    = (blockIdx.x * 256 + threadIdx.x) >> 5;
    int lane  = threadIdx.x & 31;
    int token = gw & (NTOK - 1);
    int role  = gw >> 13;                  // 0=Q, 1=K, 2=V
    const float* p = (role == 0) ? pq : (role == 1) ? pk : pv;

    float r0 = (lane == 0) ? 1.f : 0.f, i0 = 0.f, r1 = 0.f, i1 = 0.f;

    auto RY = [&](float th, int q) {
        float s, c; __sincosf(0.5f * th, &s, &c);
        if (q == 0) {
            float nr0 = c*r0 - s*r1, ni0 = c*i0 - s*i1;
            float nr1 = s*r0 + c*r1, ni1 = s*i0 + c*i1;
            r0 = nr0; i0 = ni0; r1 = nr1; i1 = ni1;
        } else {
            int m = 1 << (5 - q);
            float pr0 = shfl_x(r0, m), pi0 = shfl_x(i0, m);
            float pr1 = shfl_x(r1, m), pi1 = shfl_x(i1, m);
            float sg = (lane & m) ? s : -s;
            r0 = fmaf(sg, pr0, c*r0); i0 = fmaf(sg, pi0, c*i0);
            r1 = fmaf(sg, pr1, c*r1); i1 = fmaf(sg, pi1, c*i1);
        }
    };
    auto RZ = [&](float th, int q) {
        float s, c; __sincosf(0.5f * th, &s, &c);
        if (q == 0) {
            float nr0 = r0*c + i0*s, ni0 = i0*c - r0*s;
            float nr1 = r1*c - i1*s, ni1 = i1*c + r1*s;
            r0 = nr0; i0 = ni0; r1 = nr1; i1 = ni1;
        } else {
            int m = 1 << (5 - q);
            float sg = (lane & m) ? s : -s;
            float nr0 = r0*c - i0*sg, ni0 = i0*c + r0*sg;
            float nr1 = r1*c - i1*sg, ni1 = i1*c + r1*sg;
            r0 = nr0; i0 = ni0; r1 = nr1; i1 = ni1;
        }
    };

    #pragma unroll
    for (int q = 0; q < NQB; q++) RY(x[token * NQB + q], q);

    #pragma unroll
    for (int l = 0; l < NL; l++) {
        #pragma unroll
        for (int q = 0; q < NQB; q++) {
            RY(p[(l * NQB + q) * 2 + 0], q);
            RZ(p[(l * NQB + q) * 2 + 1], q);
        }
        r1 = shfl_x(r1, 16); i1 = shfl_x(i1, 16);
        #pragma unroll
        for (int q = 1; q <= 4; q++) {
            int cm = 1 << (5 - q), tm = 1 << (4 - q);
            float t;
            t = shfl_x(r0, tm); if (lane & cm) r0 = t;
            t = shfl_x(i0, tm); if (lane & cm) i0 = t;
            t = shfl_x(r1, tm); if (lane & cm) r1 = t;
            t = shfl_x(i1, tm); if (lane & cm) i1 = t;
        }
        if (lane & 1) { float t = r0; r0 = r1; r1 = t; t = i0; i0 = i1; i1 = t; }
    }

    if (role < 2) {
        float2* buf = (role == 0) ? (float2*)g_Q : (float2*)g_K;
        buf[token * DIM + lane]      = make_float2(r0, i0);
        buf[token * DIM + 32 + lane] = make_float2(r1, i1);
    } else {
        float p0 = r0*r0 + i0*i0;
        float p1 = r1*r1 + i1*i1;
        float v[6];
        v[0] = p0 - p1;
        #pragma unroll
        for (int q = 1; q < 6; q++) {
            float sgn = ((lane >> (5 - q)) & 1) ? -1.f : 1.f;
            v[q] = sgn * (p0 + p1);
        }
        #pragma unroll
        for (int off = 16; off >= 1; off >>= 1) {
            #pragma unroll
            for (int q = 0; q < 6; q++) v[q] += __shfl_down_sync(0xffffffffu, v[q], off);
        }
        if (lane == 0) {
            #pragma unroll
            for (int q = 0; q < 6; q++) g_V[token * 8 + q] = v[q];
            g_V[token * 8 + 6] = 0.f;
            g_V[token * 8 + 7] = 0.f;
        }
    }
}

// ---------------------------------------------------------------------------
// Phase 2: tf32 mma.sync fused attention.
// Layout: chunks kk=0..7 hold qr/kr dims (8 per chunk), kk=8..15 hold qi/ki.
// In-chunk perm p = 2*(c&3) + (c>>2): thread (lane&3)=c reads cols {c, c+4}
// as one LDS.64.  A rows = queries, B rows = keys (B frag n-index = lane>>2).
// Warps: wid&3 = m-tile (32 rows), wid>>2 = n-half (32 of 64 keys).
// ---------------------------------------------------------------------------
__global__ void __launch_bounds__(256, 1) attn_kernel()
{
    extern __shared__ float smem[];
    float* Aq = smem + AQ_OFF;   // [kk][q][8]
    float* Bs = smem + BS_OFF;   // [kk][key][8]
    float* Vs = smem + VS_OFF;   // [key][12]

    int tid   = threadIdx.x;
    int lane  = tid & 31;
    int wid   = tid >> 5;
    int warpm = wid & 3;
    int warpn = wid >> 2;
    int rr    = lane >> 2;       // group id 0..7
    int cc    = lane & 3;        // thread-in-group
    int q0    = blockIdx.x * QT;
    int key0c = blockIdx.y * KEYS_PER_CTA;

    // ---- load Q tile (128 q x 64 complex dims) into tf32 chunk layout ----
    {
        const float2* Qg = (const float2*)g_Q + (size_t)q0 * DIM;
        for (int idx = tid; idx < QT * DIM; idx += 256) {
            int q = idx >> 6, d = idx & 63;
            float2 v = Qg[(size_t)q * DIM + d];
            int kk = d >> 3, c = d & 7;
            int p = 2 * (c & 3) + (c >> 2);
            Aq[(kk * QT + q) * 8 + p]       = to_tf32(v.x);   // qr
            Aq[((kk + 8) * QT + q) * 8 + p] = to_tf32(v.y);   // qi
        }
    }

    int mrow0 = warpm * 32;

    float den[4]    = {0.f, 0.f, 0.f, 0.f};
    float vacc[4][6];
    #pragma unroll
    for (int s = 0; s < 4; s++)
        #pragma unroll
        for (int c = 0; c < 6; c++) vacc[s][c] = 0.f;

    for (int kt = 0; kt < NT_TILES; kt++) {
        int key0 = key0c + kt * KT;
        __syncthreads();   // previous tile consumed
        {
            const float2* Kg = (const float2*)g_K + (size_t)key0 * DIM;
            for (int idx = tid; idx < KT * DIM; idx += 256) {
                int k = idx >> 6, d = idx & 63;
                float2 v = Kg[(size_t)k * DIM + d];
                int kk = d >> 3, c = d & 7;
                int p = 2 * (c & 3) + (c >> 2);
                Bs[(kk * KT + k) * 8 + p]       = to_tf32(v.x);  // kr
                Bs[((kk + 8) * KT + k) * 8 + p] = to_tf32(v.y);  // ki
            }
            const float* Vg = g_V + (size_t)key0 * 8;
            for (int idx = tid; idx < KT * 6; idx += 256) {
                int k = idx / 6, c = idx - k * 6;
                Vs[k * 12 + c] = Vg[k * 8 + c];
            }
        }
        __syncthreads();

        float re[2][4][4], im[2][4][4];
        #pragma unroll
        for (int mf = 0; mf < 2; mf++)
            #pragma unroll
            for (int nf = 0; nf < 4; nf++)
                #pragma unroll
                for (int e = 0; e < 4; e++) { re[mf][nf][e] = 0.f; im[mf][nf][e] = 0.f; }

        #pragma unroll
        for (int kp = 0; kp < 8; kp++) {
            // A fragments: chunk kp (qr) and kp+8 (qi), for both m-frags
            float2 aR[2][2], aI[2][2], aRn[2][2];
            #pragma unroll
            for (int mf = 0; mf < 2; mf++) {
                int rowA = mrow0 + mf * 16 + rr;
                aR[mf][0] = *(const float2*)(Aq + ((kp * QT + rowA) * 8)      + 2 * cc);
                aR[mf][1] = *(const float2*)(Aq + ((kp * QT + rowA + 8) * 8)  + 2 * cc);
                aI[mf][0] = *(const float2*)(Aq + (((kp + 8) * QT + rowA) * 8)     + 2 * cc);
                aI[mf][1] = *(const float2*)(Aq + (((kp + 8) * QT + rowA + 8) * 8) + 2 * cc);
                aRn[mf][0] = make_float2(-aR[mf][0].x, -aR[mf][0].y);
                aRn[mf][1] = make_float2(-aR[mf][1].x, -aR[mf][1].y);
            }
            // B fragments: chunk kp (kr) and kp+8 (ki), for 4 n-frags
            float2 bR[4], bI[4];
            #pragma unroll
            for (int nf = 0; nf < 4; nf++) {
                int keyB = warpn * 32 + nf * 8 + rr;
                bR[nf] = *(const float2*)(Bs + ((kp * KT + keyB) * 8)      + 2 * cc);
                bI[nf] = *(const float2*)(Bs + (((kp + 8) * KT + keyB) * 8) + 2 * cc);
            }
            #pragma unroll
            for (int mf = 0; mf < 2; mf++) {
                #pragma unroll
                for (int nf = 0; nf < 4; nf++) {
                    // re += qr.kr + qi.ki
                    mma_tf32(re[mf][nf],
                        __float_as_uint(aR[mf][0].x), __float_as_uint(aR[mf][1].x),
                        __float_as_uint(aR[mf][0].y), __float_as_uint(aR[mf][1].y),
                        __float_as_uint(bR[nf].x),    __float_as_uint(bR[nf].y));
                    mma_tf32(re[mf][nf],
                        __float_as_uint(aI[mf][0].x), __float_as_uint(aI[mf][1].x),
                        __float_as_uint(aI[mf][0].y), __float_as_uint(aI[mf][1].y),
                        __float_as_uint(bI[nf].x),    __float_as_uint(bI[nf].y));
                    // im += qi.kr - qr.ki
                    mma_tf32(im[mf][nf],
                        __float_as_uint(aI[mf][0].x), __float_as_uint(aI[mf][1].x),
                        __float_as_uint(aI[mf][0].y), __float_as_uint(aI[mf][1].y),
                        __float_as_uint(bR[nf].x),    __float_as_uint(bR[nf].y));
                    mma_tf32(im[mf][nf],
                        __float_as_uint(aRn[mf][0].x), __float_as_uint(aRn[mf][1].x),
                        __float_as_uint(aRn[mf][0].y), __float_as_uint(aRn[mf][1].y),
                        __float_as_uint(bI[nf].x),     __float_as_uint(bI[nf].y));
                }
            }
        }

        // ---- epilogue: w = exp(re^2 + im^2); accumulate w*V and w ----
        #pragma unroll
        for (int nf = 0; nf < 4; nf++) {
            int j0 = warpn * 32 + nf * 8 + 2 * cc;     // tile-local key col (e&1==0)
            float vv[2][6];
            #pragma unroll
            for (int c = 0; c < 6; c++) {
                vv[0][c] = Vs[j0 * 12 + c];
                vv[1][c] = Vs[(j0 + 1) * 12 + c];
            }
            #pragma unroll
            for (int mf = 0; mf < 2; mf++) {
                #pragma unroll
                for (int e = 0; e < 4; e++) {
                    float r = re[mf][nf][e], i = im[mf][nf][e];
                    float l = fmaf(r, r, i * i);
                    float w = __expf(l);
                    int rs = mf * 2 + (e >> 1);
                    den[rs] += w;
                    const float* v = vv[e & 1];
                    #pragma unroll
                    for (int c = 0; c < 6; c++)
                        vacc[rs][c] = fmaf(w, v[c], vacc[rs][c]);
                }
            }
        }
    }

    // reduce across the 4 lanes (cc) sharing each query row
    #pragma unroll
    for (int off = 1; off <= 2; off <<= 1) {
        #pragma unroll
        for (int s = 0; s < 4; s++) {
            den[s] += __shfl_xor_sync(0xffffffffu, den[s], off);
            #pragma unroll
            for (int c = 0; c < 6; c++)
                vacc[s][c] += __shfl_xor_sync(0xffffffffu, vacc[s][c], off);
        }
    }
    if (cc == 0) {
        int slot = blockIdx.y * 2 + warpn;
        #pragma unroll
        for (int mf = 0; mf < 2; mf++) {
            #pragma unroll
            for (int h = 0; h < 2; h++) {
                int s  = mf * 2 + h;
                int qi = q0 + mrow0 + mf * 16 + h * 8 + rr;
                #pragma unroll
                for (int c = 0; c < 6; c++) g_part[slot][qi][c] = vacc[s][c];
                g_part[slot][qi][6] = den[s];
            }
        }
    }
}

// ---------------------------------------------------------------------------
// Phase 3: deterministic combine of the 32 partial slots + normalize.
// ---------------------------------------------------------------------------
__global__ void __launch_bounds__(256) finalize_kernel(float* __restrict__ out)
{
    int i = blockIdx.x * 256 + threadIdx.x;
    if (i >= NTOK) return;
    float den = 0.f;
    float num[6] = {0.f, 0.f, 0.f, 0.f, 0.f, 0.f};
    #pragma unroll
    for (int s = 0; s < NSLOT; s++) {
        den += g_part[s][i][6];
        #pragma unroll
        for (int c = 0; c < 6; c++) num[c] += g_part[s][i][c];
    }
    float inv = 1.f / den;
    #pragma unroll
    for (int c = 0; c < 6; c++) out[i * 6 + c] = num[c] * inv;
}

// ---------------------------------------------------------------------------
extern "C" void kernel_launch(void* const* d_in, const int* in_sizes, int n_in,
                              void* d_out, int out_size)
{
    const float* x  = (const float*)d_in[0];  // (8192, 6)
    const float* pq = (const float*)d_in[1];  // (2, 6, 2)
    const float* pk = (const float*)d_in[2];
    const float* pv = (const float*)d_in[3];
    float* out = (float*)d_out;               // (8192, 6) f32

    prep_kernel<<<(NTOK * 3) / 8, 256>>>(x, pq, pk, pv);

    size_t smem = SMEM_FLOATS * sizeof(float);
    cudaFuncSetAttribute(attn_kernel, cudaFuncAttributeMaxDynamicSharedMemorySize, (int)smem);
    attn_kernel<<<dim3(NTOK / QT, KSPL), 256, smem>>>();

    finalize_kernel<<<NTOK / 256, 256>>>(out);
}

// round 6
// speedup vs baseline: 3.8910x; 1.4553x over previous
#include <cuda_runtime.h>
#include <cuda_fp16.h>
#include <cstdint>

// ============================================================================
// SwapTestAttention on GB300 — Round 5: fp16 m16n8k16 tensor-core main loop.
//   Phase 1: warp-per-(token,role) circuit sim -> Q/K states (half2), V (f32).
//   Phase 2: fidelity via two fp16 GEMMs over K=128 real dims (f32 accum):
//              re = [Qr|Qi].[Kr|Ki]^T ; im = [Qi|-Qr].[Kr|Ki]^T
//            (fragment reuse + sign-flip; B shared). Fused epilogue:
//            w=exp(re^2+im^2), accumulate w*V and w.
//   Phase 3: deterministic combine of 32 partial slots + normalize.
// ============================================================================

#define NTOK 8192
#define NQB  6
#define DIM  64
#define NL   2

#define QT   128                 // queries per CTA
#define KT   64                  // keys per smem tile
#define KSPL 16                  // key splits (grid.y)
#define KEYS_PER_CTA (NTOK / KSPL)      // 512
#define NT_TILES (KEYS_PER_CTA / KT)    // 8
#define NSLOT 32                 // 16 splits x 2 n-warps

// smem byte offsets
#define AH_BYTES (8 * QT * 16 * 2)       // 32768: A chunks [8][128][16] half
#define BH_BYTES (8 * KT * 16 * 2)       // 16384: B chunks [8][64][16] half
#define VS_OFF   (AH_BYTES + BH_BYTES)   // V table [64][12] float
#define SMEM_BYTES (VS_OFF + KT * 12 * 4)

// Scratch (device globals; no allocation allowed)
__device__ __half2 g_Qh[NTOK * DIM];         // [token][64] (re,im)
__device__ __half2 g_Kh[NTOK * DIM];
__device__ float   g_V[NTOK * 8];            // 6 used + pad
__device__ float   g_part[NSLOT][NTOK][8];   // partial (6 acc + denom)

__device__ __forceinline__ float shfl_x(float v, int m) {
    return __shfl_xor_sync(0xffffffffu, v, m);
}
__device__ __forceinline__ void mma_f16(float d[4],
    uint32_t a0, uint32_t a1, uint32_t a2, uint32_t a3,
    uint32_t b0, uint32_t b1)
{
    asm volatile(
        "mma.sync.aligned.m16n8k16.row.col.f32.f16.f16.f32 "
        "{%0,%1,%2,%3}, {%4,%5,%6,%7}, {%8,%9}, {%0,%1,%2,%3};"
        : "+f"(d[0]), "+f"(d[1]), "+f"(d[2]), "+f"(d[3])
        : "r"(a0), "r"(a1), "r"(a2), "r"(a3), "r"(b0), "r"(b1));
}

// k-column permutation within a 16-wide chunk: col c=2j+delta -> pos
// 4*(j&3) + 2*(j>>2) + delta. Makes each thread's 4 needed halves
// (cols 2cc,2cc+1,2cc+8,2cc+9) one contiguous 8-byte LDS.64.
__device__ __forceinline__ int kperm(int c) {
    int j = c >> 1, d = c & 1;
    return 4 * (j & 3) + 2 * (j >> 2) + d;
}

// ---------------------------------------------------------------------------
// Phase 1: one warp simulates one (token, role) circuit.
// Lane l holds amplitudes of flat indices n=l (a0, bit5=0) and n=l+32 (a1).
// ---------------------------------------------------------------------------
__global__ void __launch_bounds__(256) prep_kernel(
    const float* __restrict__ x,
    const float* __restrict__ pq,
    const float* __restrict__ pk,
    const float* __restrict__ pv)
{
    int gw    = (blockIdx.x * 256 + threadIdx.x) >> 5;
    int lane  = threadIdx.x & 31;
    int token = gw & (NTOK - 1);
    int role  = gw >> 13;                  // 0=Q, 1=K, 2=V
    const float* p = (role == 0) ? pq : (role == 1) ? pk : pv;

    float r0 = (lane == 0) ? 1.f : 0.f, i0 = 0.f, r1 = 0.f, i1 = 0.f;

    auto RY = [&](float th, int q) {
        float s, c; __sincosf(0.5f * th, &s, &c);
        if (q == 0) {
            float nr0 = c*r0 - s*r1, ni0 = c*i0 - s*i1;
            float nr1 = s*r0 + c*r1, ni1 = s*i0 + c*i1;
            r0 = nr0; i0 = ni0; r1 = nr1; i1 = ni1;
        } else {
            int m = 1 << (5 - q);
            float pr0 = shfl_x(r0, m), pi0 = shfl_x(i0, m);
            float pr1 = shfl_x(r1, m), pi1 = shfl_x(i1, m);
            float sg = (lane & m) ? s : -s;
            r0 = fmaf(sg, pr0, c*r0); i0 = fmaf(sg, pi0, c*i0);
            r1 = fmaf(sg, pr1, c*r1); i1 = fmaf(sg, pi1, c*i1);
        }
    };
    auto RZ = [&](float th, int q) {
        float s, c; __sincosf(0.5f * th, &s, &c);
        if (q == 0) {
            float nr0 = r0*c + i0*s, ni0 = i0*c - r0*s;
            float nr1 = r1*c - i1*s, ni1 = i1*c + r1*s;
            r0 = nr0; i0 = ni0; r1 = nr1; i1 = ni1;
        } else {
            int m = 1 << (5 - q);
            float sg = (lane & m) ? s : -s;
            float nr0 = r0*c - i0*sg, ni0 = i0*c + r0*sg;
            float nr1 = r1*c - i1*sg, ni1 = i1*c + r1*sg;
            r0 = nr0; i0 = ni0; r1 = nr1; i1 = ni1;
        }
    };

    #pragma unroll
    for (int q = 0; q < NQB; q++) RY(x[token * NQB + q], q);

    #pragma unroll
    for (int l = 0; l < NL; l++) {
        #pragma unroll
        for (int q = 0; q < NQB; q++) {
            RY(p[(l * NQB + q) * 2 + 0], q);
            RZ(p[(l * NQB + q) * 2 + 1], q);
        }
        r1 = shfl_x(r1, 16); i1 = shfl_x(i1, 16);
        #pragma unroll
        for (int q = 1; q <= 4; q++) {
            int cm = 1 << (5 - q), tm = 1 << (4 - q);
            float t;
            t = shfl_x(r0, tm); if (lane & cm) r0 = t;
            t = shfl_x(i0, tm); if (lane & cm) i0 = t;
            t = shfl_x(r1, tm); if (lane & cm) r1 = t;
            t = shfl_x(i1, tm); if (lane & cm) i1 = t;
        }
        if (lane & 1) { float t = r0; r0 = r1; r1 = t; t = i0; i0 = i1; i1 = t; }
    }

    if (role < 2) {
        __half2* buf = (role == 0) ? g_Qh : g_Kh;
        buf[token * DIM + lane]      = __floats2half2_rn(r0, i0);
        buf[token * DIM + 32 + lane] = __floats2half2_rn(r1, i1);
    } else {
        float p0 = r0*r0 + i0*i0;
        float p1 = r1*r1 + i1*i1;
        float v[6];
        v[0] = p0 - p1;
        #pragma unroll
        for (int q = 1; q < 6; q++) {
            float sgn = ((lane >> (5 - q)) & 1) ? -1.f : 1.f;
            v[q] = sgn * (p0 + p1);
        }
        #pragma unroll
        for (int off = 16; off >= 1; off >>= 1) {
            #pragma unroll
            for (int q = 0; q < 6; q++) v[q] += __shfl_down_sync(0xffffffffu, v[q], off);
        }
        if (lane == 0) {
            #pragma unroll
            for (int q = 0; q < 6; q++) g_V[token * 8 + q] = v[q];
            g_V[token * 8 + 6] = 0.f;
            g_V[token * 8 + 7] = 0.f;
        }
    }
}

// ---------------------------------------------------------------------------
// Phase 2: fp16 m16n8k16 fused attention.
// Chunks kk=0..3: re dims (16 each); kk=4..7: im dims.
//   re += A[kp].B[kp] + A[kp+4].B[kp+4]
//   im += A[kp+4].B[kp] + (-A[kp]).B[kp+4]     for kp = 0..3
// Warps: wid&3 = m-tile (32 q rows), wid>>2 = n-half (32 of 64 keys).
// ---------------------------------------------------------------------------
__global__ void __launch_bounds__(256, 1) attn_kernel()
{
    extern __shared__ char smem[];
    __half* Ah = (__half*)smem;                 // [8][QT][16]
    __half* Bh = (__half*)(smem + AH_BYTES);    // [8][KT][16]
    float*  Vs = (float*)(smem + VS_OFF);       // [KT][12]

    int tid   = threadIdx.x;
    int lane  = tid & 31;
    int wid   = tid >> 5;
    int warpm = wid & 3;
    int warpn = wid >> 2;
    int rr    = lane >> 2;       // 0..7
    int cc    = lane & 3;        // 0..3
    int q0    = blockIdx.x * QT;
    int key0c = blockIdx.y * KEYS_PER_CTA;

    // ---- load Q tile (128 q x 64 complex dims) into fp16 chunk layout ----
    {
        const __half2* Qg = g_Qh + (size_t)q0 * DIM;
        for (int idx = tid; idx < QT * DIM; idx += 256) {
            int q = idx >> 6, d = idx & 63;
            __half2 v = Qg[(size_t)q * DIM + d];
            int kk = d >> 4, c = d & 15;
            int p = kperm(c);
            Ah[(kk * QT + q) * 16 + p]       = __low2half(v);   // qr
            Ah[((kk + 4) * QT + q) * 16 + p] = __high2half(v);  // qi
        }
    }

    int mrow0 = warpm * 32;

    float den[4] = {0.f, 0.f, 0.f, 0.f};
    float vacc[4][6];
    #pragma unroll
    for (int s = 0; s < 4; s++)
        #pragma unroll
        for (int c = 0; c < 6; c++) vacc[s][c] = 0.f;

    for (int kt = 0; kt < NT_TILES; kt++) {
        int key0 = key0c + kt * KT;
        __syncthreads();   // previous tile consumed
        {
            const __half2* Kg = g_Kh + (size_t)key0 * DIM;
            for (int idx = tid; idx < KT * DIM; idx += 256) {
                int k = idx >> 6, d = idx & 63;
                __half2 v = Kg[(size_t)k * DIM + d];
                int kk = d >> 4, c = d & 15;
                int p = kperm(c);
                Bh[(kk * KT + k) * 16 + p]       = __low2half(v);   // kr
                Bh[((kk + 4) * KT + k) * 16 + p] = __high2half(v);  // ki
            }
            const float* Vg = g_V + (size_t)key0 * 8;
            for (int idx = tid; idx < KT * 6; idx += 256) {
                int k = idx / 6, c = idx - k * 6;
                Vs[k * 12 + c] = Vg[k * 8 + c];
            }
        }
        __syncthreads();

        float re[2][4][4], im[2][4][4];
        #pragma unroll
        for (int mf = 0; mf < 2; mf++)
            #pragma unroll
            for (int nf = 0; nf < 4; nf++)
                #pragma unroll
                for (int e = 0; e < 4; e++) { re[mf][nf][e] = 0.f; im[mf][nf][e] = 0.f; }

        #pragma unroll
        for (int kp = 0; kp < 4; kp++) {
            // A fragments (4 b32 each): chunk kp = qr, chunk kp+4 = qi
            uint32_t aR[2][4], aI[2][4], aRn[2][4];
            #pragma unroll
            for (int mf = 0; mf < 2; mf++) {
                int rowA = mrow0 + mf * 16 + rr;
                uint2 lo, hi;
                lo = *(const uint2*)(Ah + (kp * QT + rowA) * 16 + 4 * cc);
                hi = *(const uint2*)(Ah + (kp * QT + rowA + 8) * 16 + 4 * cc);
                aR[mf][0] = lo.x; aR[mf][1] = hi.x; aR[mf][2] = lo.y; aR[mf][3] = hi.y;
                lo = *(const uint2*)(Ah + ((kp + 4) * QT + rowA) * 16 + 4 * cc);
                hi = *(const uint2*)(Ah + ((kp + 4) * QT + rowA + 8) * 16 + 4 * cc);
                aI[mf][0] = lo.x; aI[mf][1] = hi.x; aI[mf][2] = lo.y; aI[mf][3] = hi.y;
                #pragma unroll
                for (int e = 0; e < 4; e++) aRn[mf][e] = aR[mf][e] ^ 0x80008000u;
            }
            // B fragments (2 b32 each): chunk kp = kr, chunk kp+4 = ki
            uint2 bR[4], bI[4];
            #pragma unroll
            for (int nf = 0; nf < 4; nf++) {
                int keyB = warpn * 32 + nf * 8 + rr;
                bR[nf] = *(const uint2*)(Bh + (kp * KT + keyB) * 16 + 4 * cc);
                bI[nf] = *(const uint2*)(Bh + ((kp + 4) * KT + keyB) * 16 + 4 * cc);
            }
            #pragma unroll
            for (int mf = 0; mf < 2; mf++) {
                #pragma unroll
                for (int nf = 0; nf < 4; nf++) {
                    // re += qr.kr + qi.ki
                    mma_f16(re[mf][nf], aR[mf][0], aR[mf][1], aR[mf][2], aR[mf][3],
                            bR[nf].x, bR[nf].y);
                    mma_f16(re[mf][nf], aI[mf][0], aI[mf][1], aI[mf][2], aI[mf][3],
                            bI[nf].x, bI[nf].y);
                    // im += qi.kr - qr.ki
                    mma_f16(im[mf][nf], aI[mf][0], aI[mf][1], aI[mf][2], aI[mf][3],
                            bR[nf].x, bR[nf].y);
                    mma_f16(im[mf][nf], aRn[mf][0], aRn[mf][1], aRn[mf][2], aRn[mf][3],
                            bI[nf].x, bI[nf].y);
                }
            }
        }

        // ---- epilogue: w = exp(re^2 + im^2); accumulate w*V and w ----
        #pragma unroll
        for (int nf = 0; nf < 4; nf++) {
            int j0 = warpn * 32 + nf * 8 + 2 * cc;
            float vv[2][6];
            #pragma unroll
            for (int c = 0; c < 6; c++) {
                vv[0][c] = Vs[j0 * 12 + c];
                vv[1][c] = Vs[(j0 + 1) * 12 + c];
            }
            #pragma unroll
            for (int mf = 0; mf < 2; mf++) {
                #pragma unroll
                for (int e = 0; e < 4; e++) {
                    float r = re[mf][nf][e], i = im[mf][nf][e];
                    float l = fmaf(r, r, i * i);
                    float w = __expf(l);
                    int rs = mf * 2 + (e >> 1);
                    den[rs] += w;
                    const float* v = vv[e & 1];
                    #pragma unroll
                    for (int c = 0; c < 6; c++)
                        vacc[rs][c] = fmaf(w, v[c], vacc[rs][c]);
                }
            }
        }
    }

    // reduce across the 4 lanes (cc) sharing each query row
    #pragma unroll
    for (int off = 1; off <= 2; off <<= 1) {
        #pragma unroll
        for (int s = 0; s < 4; s++) {
            den[s] += __shfl_xor_sync(0xffffffffu, den[s], off);
            #pragma unroll
            for (int c = 0; c < 6; c++)
                vacc[s][c] += __shfl_xor_sync(0xffffffffu, vacc[s][c], off);
        }
    }
    if (cc == 0) {
        int slot = blockIdx.y * 2 + warpn;
        #pragma unroll
        for (int mf = 0; mf < 2; mf++) {
            #pragma unroll
            for (int h = 0; h < 2; h++) {
                int s  = mf * 2 + h;
                int qi = q0 + mrow0 + mf * 16 + h * 8 + rr;
                #pragma unroll
                for (int c = 0; c < 6; c++) g_part[slot][qi][c] = vacc[s][c];
                g_part[slot][qi][6] = den[s];
            }
        }
    }
}

// ---------------------------------------------------------------------------
// Phase 3: deterministic combine of the 32 partial slots + normalize.
// ---------------------------------------------------------------------------
__global__ void __launch_bounds__(256) finalize_kernel(float* __restrict__ out)
{
    int i = blockIdx.x * 256 + threadIdx.x;
    if (i >= NTOK) return;
    float den = 0.f;
    float num[6] = {0.f, 0.f, 0.f, 0.f, 0.f, 0.f};
    #pragma unroll
    for (int s = 0; s < NSLOT; s++) {
        den += g_part[s][i][6];
        #pragma unroll
        for (int c = 0; c < 6; c++) num[c] += g_part[s][i][c];
    }
    float inv = 1.f / den;
    #pragma unroll
    for (int c = 0; c < 6; c++) out[i * 6 + c] = num[c] * inv;
}

// ---------------------------------------------------------------------------
extern "C" void kernel_launch(void* const* d_in, const int* in_sizes, int n_in,
                              void* d_out, int out_size)
{
    const float* x  = (const float*)d_in[0];  // (8192, 6)
    const float* pq = (const float*)d_in[1];  // (2, 6, 2)
    const float* pk = (const float*)d_in[2];
    const float* pv = (const float*)d_in[3];
    float* out = (float*)d_out;               // (8192, 6) f32

    prep_kernel<<<(NTOK * 3) / 8, 256>>>(x, pq, pk, pv);

    cudaFuncSetAttribute(attn_kernel, cudaFuncAttributeMaxDynamicSharedMemorySize, SMEM_BYTES);
    attn_kernel<<<dim3(NTOK / QT, KSPL), 256, SMEM_BYTES>>>();

    finalize_kernel<<<NTOK / 256, 256>>>(out);
}